// round 16
// baseline (speedup 1.0000x reference)
#include <cuda_runtime.h>

// Problem constants (fixed by the reference)
constexpr int B  = 8;
constexpr int C  = 256;
constexpr int H  = 64;
constexpr int W  = 64;
constexpr int WC = 16;           // weight channels
constexpr int G  = C / WC;       // 16 groups sharing each weight
constexpr int HW = H * W;        // 4096
constexpr int Q  = HW / 4;       // float4 quads per plane = 1024
constexpr int GSTRIDE = WC * HW; // plane stride between groups (65536 floats)

// Non-hoistable LDG.128 (asm volatile defeats loop-invariant code motion,
// keeping the streamed weight set OUT of the resident register file).
__device__ __forceinline__ float4 ldg4_volatile(const float4* p) {
    float4 v;
    asm volatile("ld.global.nc.v4.f32 {%0,%1,%2,%3}, [%4];"
                 : "=f"(v.x), "=f"(v.y), "=f"(v.z), "=f"(v.w) : "l"(p));
    return v;
}

// v6 structure (2-row vertical tile, dist-1 x prefetch, shuffle neighbors)
// with HALF the weight set streamed from L1 each group instead of held in
// registers: regs ~110 -> 9 CTAs/SM -> 18 warps/SM (vs v6's ~13), single
// wave (1024 CTAs <= 1332). Streamed weights are same-address every group
// => L1 hits, latency covered by the extra warps.
__global__ __launch_bounds__(64, 9) void agg_kernel_v13(
    const float* __restrict__ x,
    const float* __restrict__ w,
    float* __restrict__ out)
{
    const int idx  = blockIdx.x * 64 + threadIdx.x;  // 0 .. 65535
    const int q2   = idx & 511;            // 32 row-pairs x 16 quad-cols
    const int wc   = (idx >> 9) & (WC - 1);
    const int b    = idx >> 13;
    const int qcol = q2 & 15;
    const int oh   = (q2 >> 4) << 1;       // even output row
    const int p4   = oh * W + qcol * 4;    // first pixel of top quad

    const float mL = (qcol == 0)  ? 0.f : 1.f;
    const float mR = (qcol == 15) ? 0.f : 1.f;
    const bool ym  = (oh > 0);             // x row oh-1 exists
    const bool yp  = (oh < H - 2);         // x row oh+2 exists

    // Resident weights: 9 taps for output row oh only (36 regs).
    const float4* wp = (const float4*)(w + ((size_t)(b * WC + wc) * 9) * HW + p4);
    float4 wv0[9];
    #pragma unroll
    for (int t = 0; t < 9; t++) wv0[t] = wp[(size_t)t * Q];
    // Streamed weights: row oh+1 taps, re-read from L1 every group.
    const float4* wp1 = wp + 16;           // +64 floats = next row

    const float* xc = x   + (size_t)(b * C + wc) * HW + p4;  // group-0 top quad
    float*       op = out + (size_t)(b * C + wc) * HW + p4;

    const float4 z4 = make_float4(0.f, 0.f, 0.f, 0.f);

    auto load_rows = [&](float4* c, const float* p) {
        c[0] = ym ? *(const float4*)(p - W)     : z4;
        c[1] =      *(const float4*)(p);
        c[2] =      *(const float4*)(p + W);
        c[3] = yp ? *(const float4*)(p + 2 * W) : z4;
    };

    auto tap = [&](float4& acc, const float4 cc, float lf, float rt,
                   const float4 wl, const float4 wm, const float4 wr) {
        acc.x += lf   * wl.x + cc.x * wm.x + cc.y * wr.x;
        acc.y += cc.x * wl.y + cc.y * wm.y + cc.z * wr.y;
        acc.z += cc.y * wl.z + cc.z * wm.z + cc.w * wr.z;
        acc.w += cc.z * wl.w + cc.w * wm.w + rt   * wr.w;
    };

    float4 buf0[4], buf1[4];
    load_rows(buf0, xc);

    #pragma unroll 2
    for (int g = 0; g < G; g++) {
        float4* c = (g & 1) ? buf1 : buf0;
        float4* n = (g & 1) ? buf0 : buf1;

        // Prefetch next group's x rows before computing this one.
        xc += GSTRIDE;
        if (g < G - 1) load_rows(n, xc);

        // Horizontal neighbors for all 4 rows (shared by both outputs).
        float lf[4], rt[4];
        #pragma unroll
        for (int a = 0; a < 4; a++) {
            lf[a] = __shfl_up_sync  (0xffffffffu, c[a].w, 1) * mL;
            rt[a] = __shfl_down_sync(0xffffffffu, c[a].x, 1) * mR;
        }

        float4 acc0 = z4, acc1 = z4;

        #pragma unroll
        for (int r = 0; r < 3; r++) {
            // Output row oh: resident weights.
            tap(acc0, c[r], lf[r], rt[r],
                wv0[3 * r + 0], wv0[3 * r + 1], wv0[3 * r + 2]);

            // Output row oh+1: weights streamed from L1 (short lives).
            const float4 u0 = ldg4_volatile(wp1 + (size_t)(3 * r + 0) * Q);
            const float4 u1 = ldg4_volatile(wp1 + (size_t)(3 * r + 1) * Q);
            const float4 u2 = ldg4_volatile(wp1 + (size_t)(3 * r + 2) * Q);
            tap(acc1, c[r + 1], lf[r + 1], rt[r + 1], u0, u1, u2);
        }

        *(float4*)(op)     = acc0;
        *(float4*)(op + W) = acc1;
        op += GSTRIDE;
    }
}

extern "C" void kernel_launch(void* const* d_in, const int* in_sizes, int n_in,
                              void* d_out, int out_size)
{
    const float* x = (const float*)d_in[0];   // (8,256,64,64) f32
    const float* w = (const float*)d_in[1];   // (8,16,9,4096) f32
    float* out = (float*)d_out;               // (8,256,64,64) f32

    const int total = B * WC * (Q / 2);       // 65536 threads (2 rows each)
    agg_kernel_v13<<<total / 64, 64>>>(x, w, out);
}

// round 17
// speedup vs baseline: 2.0622x; 2.0622x over previous
#include <cuda_runtime.h>

// Problem constants (fixed by the reference)
constexpr int B  = 8;
constexpr int C  = 256;
constexpr int H  = 64;
constexpr int W  = 64;
constexpr int WC = 16;           // weight channels
constexpr int G  = C / WC;       // 16 groups sharing each weight
constexpr int HW = H * W;        // 4096
constexpr int Q  = HW / 4;       // float4 quads per plane = 1024
constexpr int GSTRIDE = WC * HW; // plane stride between groups (65536 floats)

constexpr int GCHUNK = 8;        // groups per thread (16 split across 2 threads)

// v6 compute structure (2-row vertical tile, 18 weight float4s register-
// resident, distance-1 x prefetch, shuffle horizontal neighbors), but each
// thread covers only 8 of the 16 groups -> 2048 CTAs instead of 1024.
// v6's grid (1024) supplied only ~6.9 CTAs/SM against an 8-CTA residency
// cap (regs=128); doubling the CTA count keeps every SM at its full
// 16-warp occupancy cap for most of the kernel. Weights are (re)loaded by
// both chunk-threads of a row pair: +19MB L2-side traffic, DRAM unchanged.
__global__ __launch_bounds__(64, 7) void agg_kernel_v14(
    const float* __restrict__ x,
    const float* __restrict__ w,
    float* __restrict__ out)
{
    const int idx  = blockIdx.x * 64 + threadIdx.x;  // 0 .. 131071
    const int q2   = idx & 511;            // 32 row-pairs x 16 quad-cols
    const int wc   = (idx >> 9) & (WC - 1);
    const int b    = (idx >> 13) & 7;
    const int chunk = idx >> 16;           // 0: groups 0-7, 1: groups 8-15
    const int qcol = q2 & 15;
    const int oh   = (q2 >> 4) << 1;       // even output row
    const int p4   = oh * W + qcol * 4;    // first pixel of top quad

    const float mL = (qcol == 0)  ? 0.f : 1.f;
    const float mR = (qcol == 15) ? 0.f : 1.f;
    const bool ym  = (oh > 0);             // x row oh-1 exists
    const bool yp  = (oh < H - 2);         // x row oh+2 exists

    // Weights: 9 taps for output row oh (wv0) and row oh+1 (wv1).
    const float4* wp = (const float4*)(w + ((size_t)(b * WC + wc) * 9) * HW + p4);
    float4 wv0[9], wv1[9];
    #pragma unroll
    for (int t = 0; t < 9; t++) {
        wv0[t] = wp[(size_t)t * Q];
        wv1[t] = wp[(size_t)t * Q + 16];   // +64 floats = next row
    }

    // Start at this thread's first group (chunk * GCHUNK).
    const size_t plane = (size_t)(b * C + wc) * HW + p4
                       + (size_t)chunk * GCHUNK * GSTRIDE;
    const float* xc = x   + plane;
    float*       op = out + plane;

    const float4 z4 = make_float4(0.f, 0.f, 0.f, 0.f);

    auto load_rows = [&](float4* c, const float* p) {
        c[0] = ym ? *(const float4*)(p - W)     : z4;
        c[1] =      *(const float4*)(p);
        c[2] =      *(const float4*)(p + W);
        c[3] = yp ? *(const float4*)(p + 2 * W) : z4;
    };

    float4 buf0[4], buf1[4];
    load_rows(buf0, xc);

    #pragma unroll
    for (int g = 0; g < GCHUNK; g++) {
        float4* c = (g & 1) ? buf1 : buf0;
        float4* n = (g & 1) ? buf0 : buf1;

        // Prefetch next group's rows before computing this one.
        xc += GSTRIDE;
        if (g < GCHUNK - 1) load_rows(n, xc);

        float4 acc0 = z4, acc1 = z4;

        #pragma unroll
        for (int a = 0; a < 4; a++) {
            const float4 cc = c[a];
            const float lf = __shfl_up_sync  (0xffffffffu, cc.w, 1) * mL;
            const float rt = __shfl_down_sync(0xffffffffu, cc.x, 1) * mR;

            if (a < 3) {   // contributes to output row oh via tap row a
                const float4 wl = wv0[3 * a + 0];
                const float4 wm = wv0[3 * a + 1];
                const float4 wr = wv0[3 * a + 2];
                acc0.x += lf   * wl.x + cc.x * wm.x + cc.y * wr.x;
                acc0.y += cc.x * wl.y + cc.y * wm.y + cc.z * wr.y;
                acc0.z += cc.y * wl.z + cc.z * wm.z + cc.w * wr.z;
                acc0.w += cc.z * wl.w + cc.w * wm.w + rt   * wr.w;
            }
            if (a > 0) {   // contributes to output row oh+1 via tap row a-1
                const float4 wl = wv1[3 * (a - 1) + 0];
                const float4 wm = wv1[3 * (a - 1) + 1];
                const float4 wr = wv1[3 * (a - 1) + 2];
                acc1.x += lf   * wl.x + cc.x * wm.x + cc.y * wr.x;
                acc1.y += cc.x * wl.y + cc.y * wm.y + cc.z * wr.y;
                acc1.z += cc.y * wl.z + cc.z * wm.z + cc.w * wr.z;
                acc1.w += cc.z * wl.w + cc.w * wm.w + rt   * wr.w;
            }
        }

        *(float4*)(op)     = acc0;
        *(float4*)(op + W) = acc1;
        op += GSTRIDE;
    }
}

extern "C" void kernel_launch(void* const* d_in, const int* in_sizes, int n_in,
                              void* d_out, int out_size)
{
    const float* x = (const float*)d_in[0];   // (8,256,64,64) f32
    const float* w = (const float*)d_in[1];   // (8,16,9,4096) f32
    float* out = (float*)d_out;               // (8,256,64,64) f32

    const int total = B * WC * (Q / 2) * (G / GCHUNK);  // 131072 threads
    agg_kernel_v14<<<total / 64, 64>>>(x, w, out);
}